// round 15
// baseline (speedup 1.0000x reference)
#include <cuda_runtime.h>
#include <cuda_fp16.h>
#include <stdint.h>
#include <math.h>

// Problem shape (fixed)
#define Bn 4
#define Ln 8192
#define Dn 1024
#define BLn (Bn * Ln)   // 32768 tokens
#define MAXFIX 512

// ---------------------------------------------------------------------------
// Scratch (device globals)
// ---------------------------------------------------------------------------
__device__ __half g_qh[(size_t)BLn * Dn];           // 64 MB (32*q as fp16)
__device__ __half g_kh[(size_t)BLn * Dn];           // 64 MB (32*k as fp16)
__device__ __half g_xh[(size_t)BLn * Dn];           // 64 MB (x as fp16)
__device__ __half g_wh[2][(size_t)Dn * Dn];         // 4 MB  (32*Wq, 32*Wk fp16)
__device__ int    g_src[BLn];
__device__ int    g_len[Bn];
__device__ double g_sumP[Bn];
__device__ int    g_nfix;
__device__ int    g_fix[MAXFIX];
__device__ double g_fixacc[3][MAXFIX];

// ---------------------------------------------------------------------------
// helpers
// ---------------------------------------------------------------------------
__device__ __forceinline__ uint32_t cvta_shared_u32(const void* p) {
    uint32_t r;
    asm("{ .reg .u64 t; cvta.to.shared.u64 t, %1; cvt.u32.u64 %0, t; }"
        : "=r"(r) : "l"(p));
    return r;
}
#define LDMATRIX_X4(r0, r1, r2, r3, addr)                                  \
    asm volatile("ldmatrix.sync.aligned.m8n8.x4.shared.b16 {%0,%1,%2,%3}, [%4];" \
                 : "=r"(r0), "=r"(r1), "=r"(r2), "=r"(r3) : "r"(addr))
#define MMA16816(c0, c1, c2, c3, a0, a1, a2, a3, b0, b1)                   \
    asm volatile("mma.sync.aligned.m16n8k16.row.col.f32.f16.f16.f32 "      \
                 "{%0,%1,%2,%3}, {%4,%5,%6,%7}, {%8,%9}, {%0,%1,%2,%3};"   \
                 : "+f"(c0), "+f"(c1), "+f"(c2), "+f"(c3)                  \
                 : "r"(a0), "r"(a1), "r"(a2), "r"(a3), "r"(b0), "r"(b1))
#define CP_ASYNC16(saddr, gaddr)                                           \
    asm volatile("cp.async.cg.shared.global [%0], [%1], 16;"               \
                 :: "r"(saddr), "l"(gaddr))

// ---------------------------------------------------------------------------
// Fused converts: Wq, Wk -> fp16 scaled by 32; x -> fp16.
// ---------------------------------------------------------------------------
#define WN4 (Dn * Dn / 4)       // 262144
#define XN4 (BLn * Dn / 4)      // 8388608

__global__ void conv_all_kernel(const float* __restrict__ x,
                                const float* __restrict__ Wq,
                                const float* __restrict__ Wk)
{
    const int i = blockIdx.x * blockDim.x + threadIdx.x;
    if (i == 0) g_nfix = 0;     // reset fixup list each replay

    if (i < 2 * WN4) {
        const int which = i >> 18;            // 0: Wq, 1: Wk
        const int jj    = i & (WN4 - 1);
        const float4 v = ((const float4*)(which ? Wk : Wq))[jj];
        const __half2 h0 = __floats2half2_rn(32.0f * v.x, 32.0f * v.y);
        const __half2 h1 = __floats2half2_rn(32.0f * v.z, 32.0f * v.w);
        uint2 u;
        u.x = *(const uint32_t*)&h0;
        u.y = *(const uint32_t*)&h1;
        ((uint2*)&g_wh[which][0])[jj] = u;
    } else {
        const int jj = i - 2 * WN4;
        if (jj < XN4) {
            const float4 v = ((const float4*)x)[jj];
            const __half2 h0 = __floats2half2_rn(v.x, v.y);
            const __half2 h1 = __floats2half2_rn(v.z, v.w);
            uint2 u;
            u.x = *(const uint32_t*)&h0;
            u.y = *(const uint32_t*)&h1;
            ((uint2*)&g_xh[0])[jj] = u;
        }
    }
}

// ---------------------------------------------------------------------------
// HMMA fp16 GEMM (single product): C = X * W^T, C stored as fp16.
// Tile 128x128, BK=64 (128B rows, XOR swizzle), 256 threads (8 warps 2x4),
// warp tile 64x32.  2 smem buffers, loads issued then wait_group 1 (R13).
// grid = (8 n-tiles, 256 m-tiles, 2 gemms).
// ---------------------------------------------------------------------------
#define SIDE_BYTES  16384                  // 128 rows * 128 B
#define BUF_BYTES   (2 * SIDE_BYTES)       // 32768 (A side + B side)
#define GEMM_SMEM   (2 * BUF_BYTES)        // 65536

// swizzled byte offset of 16B unit u (0..7) in row r (128B rows)
__device__ __forceinline__ uint32_t sw_off(int r, int u) {
    return (uint32_t)(128 * r + 16 * (u ^ (r & 7)));
}

__global__ __launch_bounds__(256, 2)
void hgemm_kernel()
{
    extern __shared__ char smem[];
    const uint32_t sbase = cvta_shared_u32(smem);

    const int tid  = threadIdx.x;
    const int wid  = tid >> 5;
    const int lane = tid & 31;
    const int wm   = wid & 1;          // 0..1 : 64-row half
    const int wn   = wid >> 1;         // 0..3 : 32-col quarter
    const int tn = blockIdx.x, tm = blockIdx.y, gz = blockIdx.z;

    const int j    = lane >> 3;        // ldmatrix matrix id 0..3
    const int rlow = lane & 7;

    int rA[4], rB[2];
    #pragma unroll
    for (int mt = 0; mt < 4; mt++)
        rA[mt] = wm * 64 + mt * 16 + (j & 1) * 8 + rlow;
    #pragma unroll
    for (int g = 0; g < 2; g++)
        rB[g] = wn * 32 + g * 16 + (j & 1) * 8 + rlow;
    const int jhi = j >> 1;

    float acc[4][4][4];
    #pragma unroll
    for (int mt = 0; mt < 4; mt++)
        #pragma unroll
        for (int nt = 0; nt < 4; nt++)
            #pragma unroll
            for (int e = 0; e < 4; e++) acc[mt][nt][e] = 0.0f;

    const char* xbase = (const char*)&g_xh[0] + (size_t)(tm * 128) * (Dn * 2);
    const char* wbase = (const char*)&g_wh[gz][0] + (size_t)(tn * 128) * (Dn * 2);

    // loader: 8 x 16B units per thread per chunk (2048 units total)
    int l_side[8], l_r[8], l_u[8];
    #pragma unroll
    for (int i = 0; i < 8; i++) {
        const int v    = tid + i * 256;
        const int side = v >= 1024;
        const int w    = v & 1023;
        l_side[i] = side;
        l_r[i]    = w >> 3;
        l_u[i]    = w & 7;
    }

    #define LOAD_CHUNK(buf, c)                                                   \
    do {                                                                         \
        const uint32_t bb = sbase + (buf) * BUF_BYTES;                           \
        _Pragma("unroll")                                                        \
        for (int i = 0; i < 8; i++) {                                            \
            const uint32_t sa = bb + l_side[i] * SIDE_BYTES +                    \
                                sw_off(l_r[i], l_u[i]);                          \
            const char* ga = (l_side[i] ? wbase : xbase) +                       \
                             (size_t)l_r[i] * (Dn * 2) + (c) * 128 + l_u[i] * 16;\
            CP_ASYNC16(sa, ga);                                                  \
        }                                                                        \
        asm volatile("cp.async.commit_group;");                                  \
    } while (0)

    const int NCH = Dn / 64;   // 16 chunks
    LOAD_CHUNK(0, 0);

    for (int c = 0; c < NCH; c++) {
        const int buf = c & 1;
        if (c + 1 < NCH) {
            LOAD_CHUNK(buf ^ 1, c + 1);
            asm volatile("cp.async.wait_group 1;");
        } else {
            asm volatile("cp.async.wait_group 0;");
        }
        __syncthreads();

        const uint32_t aB = sbase + buf * BUF_BYTES;
        const uint32_t bB = aB + SIDE_BYTES;

        #pragma unroll
        for (int ks = 0; ks < 4; ks++) {
            uint32_t bfr[4][2];
            #pragma unroll
            for (int g = 0; g < 2; g++) {
                uint32_t r0, r1, r2, r3;
                const uint32_t addr = bB + 128 * rB[g] +
                    16 * ((2 * ks + jhi) ^ (rB[g] & 7));
                LDMATRIX_X4(r0, r1, r2, r3, addr);
                bfr[2 * g + 0][0] = r0; bfr[2 * g + 0][1] = r2;
                bfr[2 * g + 1][0] = r1; bfr[2 * g + 1][1] = r3;
            }
            uint32_t afr[4][4];
            #pragma unroll
            for (int mt = 0; mt < 4; mt++) {
                const uint32_t addr = aB + 128 * rA[mt] +
                    16 * ((2 * ks + jhi) ^ (rA[mt] & 7));
                LDMATRIX_X4(afr[mt][0], afr[mt][1], afr[mt][2], afr[mt][3], addr);
            }
            #pragma unroll
            for (int mt = 0; mt < 4; mt++)
                #pragma unroll
                for (int nt = 0; nt < 4; nt++)
                    MMA16816(acc[mt][nt][0], acc[mt][nt][1],
                             acc[mt][nt][2], acc[mt][nt][3],
                             afr[mt][0], afr[mt][1], afr[mt][2], afr[mt][3],
                             bfr[nt][0], bfr[nt][1]);
        }
        __syncthreads();
    }

    // epilogue: store as fp16 (values are 32x true q/k; cos is scale-inv)
    __half* C = (gz == 0) ? g_qh : g_kh;
    const int rowb = tm * 128 + wm * 64 + (lane >> 2);
    const int colb = tn * 128 + wn * 32 + 2 * (lane & 3);
    #pragma unroll
    for (int mt = 0; mt < 4; mt++) {
        #pragma unroll
        for (int nt = 0; nt < 4; nt++) {
            const size_t r0 = (size_t)(rowb + mt * 16) * Dn + colb + nt * 8;
            const __half2 lo = __floats2half2_rn(acc[mt][nt][0], acc[mt][nt][1]);
            const __half2 hi = __floats2half2_rn(acc[mt][nt][2], acc[mt][nt][3]);
            *(__half2*)&C[r0]          = lo;
            *(__half2*)&C[r0 + 8 * Dn] = hi;
        }
    }
    #undef LOAD_CHUNK
}

// ---------------------------------------------------------------------------
// Per-token props: warp per token, fp16 q/k reads, fp32 math, shfl-only.
// ---------------------------------------------------------------------------
__global__ void props_kernel(float* __restrict__ out_p, float* __restrict__ out_b)
{
    const int t    = blockIdx.x * 8 + (threadIdx.x >> 5);
    const int lane = threadIdx.x & 31;

    if ((t & (Ln - 1)) == 0) {
        if (lane == 0) { out_p[t] = 1.0f; out_b[t] = 1.0f; }
        return;
    }
    const uint4* qr = (const uint4*)(g_qh + (size_t)t * Dn);
    const uint4* kr = (const uint4*)(g_kh + (size_t)(t - 1) * Dn);

    float sq = 0.f, sk = 0.f, sp = 0.f;
    #pragma unroll
    for (int i = 0; i < 4; i++) {
        const uint4 qu = qr[lane + i * 32];
        const uint4 ku = kr[lane + i * 32];
        const uint32_t qa[4] = {qu.x, qu.y, qu.z, qu.w};
        const uint32_t ka[4] = {ku.x, ku.y, ku.z, ku.w};
        #pragma unroll
        for (int c = 0; c < 4; c++) {
            const float2 qf = __half22float2(*(const __half2*)&qa[c]);
            const float2 kf = __half22float2(*(const __half2*)&ka[c]);
            sq = fmaf(qf.x, qf.x, sq); sq = fmaf(qf.y, qf.y, sq);
            sk = fmaf(kf.x, kf.x, sk); sk = fmaf(kf.y, kf.y, sk);
            sp = fmaf(qf.x, kf.x, sp); sp = fmaf(qf.y, kf.y, sp);
        }
    }
    #pragma unroll
    for (int o = 16; o > 0; o >>= 1) {
        sq += __shfl_down_sync(0xffffffffu, sq, o);
        sk += __shfl_down_sync(0xffffffffu, sk, o);
        sp += __shfl_down_sync(0xffffffffu, sp, o);
    }
    if (lane == 0) {
        const float nq = fmaxf(sqrtf(sq), 1e-12f);
        const float nk = fmaxf(sqrtf(sk), 1e-12f);
        const float cs = sp / (nq * nk);
        const float pv = 0.5f * (1.0f - cs);
        out_p[t] = pv;
        out_b[t] = (pv >= 0.5f) ? 1.0f : 0.0f;
        if (fabsf(cs) < 1e-4f) {
            const int ix = atomicAdd(&g_nfix, 1);
            if (ix < MAXFIX) {
                g_fix[ix] = t;
                g_fixacc[0][ix] = 0.0;
                g_fixacc[1][ix] = 0.0;
                g_fixacc[2][ix] = 0.0;
            }
        }
    }
}

// ---------------------------------------------------------------------------
// Fixup stage 1 (W-stationary): grid = 128 blocks, each owns 8 E-rows.
// Each warp keeps its Wq/Wk row in registers; loop over flagged tokens,
// streaming only x rows.  Per-token block reduction in smem, 3 atomics by
// thread 0.  Row dots fp32; squares in fp64.
// ---------------------------------------------------------------------------
__global__ __launch_bounds__(256)
void fixup_partial_kernel(const float* __restrict__ x,
                          const float* __restrict__ Wq,
                          const float* __restrict__ Wk)
{
    const int nf = (g_nfix < MAXFIX) ? g_nfix : MAXFIX;
    if (nf == 0) return;
    const int tid  = threadIdx.x;
    const int lane = tid & 31, wrp = tid >> 5;
    const int e    = blockIdx.x * 8 + wrp;     // this warp's E-row

    // W rows -> registers (coalesced float4 loads)
    float4 wq[8], wk[8];
    const float4* wqp = (const float4*)(Wq + (size_t)e * Dn);
    const float4* wkp = (const float4*)(Wk + (size_t)e * Dn);
    #pragma unroll
    for (int jj = 0; jj < 8; jj++) {
        wq[jj] = wqp[lane + jj * 32];
        wk[jj] = wkp[lane + jj * 32];
    }

    __shared__ float xs[Dn], xp[Dn];
    __shared__ float qsh[8], ksh[8];

    for (int it = 0; it < nf; it++) {
        const int t = g_fix[it];
        __syncthreads();                        // xs/qsh free from prev iter
        for (int d = tid; d < Dn; d += 256) {
            xs[d] = x[(size_t)t * Dn + d];
            xp[d] = x[(size_t)(t - 1) * Dn + d];
        }
        __syncthreads();

        float qd = 0.f, kd = 0.f;
        #pragma unroll
        for (int jj = 0; jj < 8; jj++) {
            const int d0 = (lane + jj * 32) * 4;
            const float4 a = *(const float4*)&xs[d0];
            const float4 b = *(const float4*)&xp[d0];
            qd = fmaf(a.x, wq[jj].x, qd); qd = fmaf(a.y, wq[jj].y, qd);
            qd = fmaf(a.z, wq[jj].z, qd); qd = fmaf(a.w, wq[jj].w, qd);
            kd = fmaf(b.x, wk[jj].x, kd); kd = fmaf(b.y, wk[jj].y, kd);
            kd = fmaf(b.z, wk[jj].z, kd); kd = fmaf(b.w, wk[jj].w, kd);
        }
        #pragma unroll
        for (int o = 16; o > 0; o >>= 1) {
            qd += __shfl_down_sync(0xffffffffu, qd, o);
            kd += __shfl_down_sync(0xffffffffu, kd, o);
        }
        if (lane == 0) { qsh[wrp] = qd; ksh[wrp] = kd; }
        __syncthreads();
        if (tid == 0) {
            double sq = 0.0, sk = 0.0, sp = 0.0;
            #pragma unroll
            for (int w = 0; w < 8; w++) {
                const double q = (double)qsh[w], k2 = (double)ksh[w];
                sq += q * q; sk += k2 * k2; sp += q * k2;
            }
            atomicAdd(&g_fixacc[0][it], sq);
            atomicAdd(&g_fixacc[1][it], sk);
            atomicAdd(&g_fixacc[2][it], sp);
        }
    }
}

// Fixup stage 2: decide b from the exact sums.
__global__ void fixup_apply_kernel(float* __restrict__ out_b)
{
    const int i = threadIdx.x;
    const int nf = (g_nfix < MAXFIX) ? g_nfix : MAXFIX;
    if (i < nf) {
        const double cs = g_fixacc[2][i] / sqrt(g_fixacc[0][i] * g_fixacc[1][i]);
        out_b[g_fix[i]] = (cs <= 0.0) ? 1.0f : 0.0f;
    }
}

// ---------------------------------------------------------------------------
// Per-batch scan of b — b/p staged through smem with coalesced loads.
// ---------------------------------------------------------------------------
__global__ void scan_kernel(const float* __restrict__ p_arr,
                            const float* __restrict__ b_arr,
                            float* __restrict__ P_down,
                            float* __restrict__ out_len)
{
    extern __shared__ float sc[];           // [0,Ln): b, [Ln,2Ln): p
    float* sb = sc;
    float* sp_ = sc + Ln;

    const int batch = blockIdx.x;
    const int tid   = threadIdx.x;
    const float4* bb4 = (const float4*)(b_arr + batch * Ln);
    const float4* pp4 = (const float4*)(p_arr + batch * Ln);
    #pragma unroll
    for (int i = 0; i < Ln / 4 / 256; i++) {
        const int idx = tid + i * 256;
        *(float4*)&sb[idx * 4]  = bb4[idx];
        *(float4*)&sp_[idx * 4] = pp4[idx];
    }
    __syncthreads();

    const int base = tid * 32;
    int    cnt  = 0;
    double sump = 0.0;
    #pragma unroll 8
    for (int jj = 0; jj < 32; jj++) {
        cnt  += (sb[base + jj] > 0.5f) ? 1 : 0;
        sump += (double)sp_[base + jj];
    }
    const int lane = tid & 31, wid = tid >> 5;
    int v = cnt;
    #pragma unroll
    for (int o = 1; o < 32; o <<= 1) {
        const int n = __shfl_up_sync(0xffffffffu, v, o);
        if (lane >= o) v += n;
    }
    __shared__ int wsum[8], woff[8], stotal;
    if (lane == 31) wsum[wid] = v;
    __syncthreads();
    if (tid == 0) {
        int s = 0;
        for (int w = 0; w < 8; w++) { woff[w] = s; s += wsum[w]; }
        stotal = s;
    }
    __syncthreads();

    int slot = woff[wid] + v - cnt;
    const int total = stotal;

    for (int jj = 0; jj < 32; jj++) {
        if (sb[base + jj] > 0.5f) {
            const int l = base + jj;
            g_src[batch * Ln + slot]  = l;
            P_down[batch * Ln + slot] = sp_[l];
            slot++;
        }
    }
    for (int s = total + tid; s < Ln; s += 256)
        P_down[batch * Ln + s] = 0.0f;

    #pragma unroll
    for (int o = 16; o > 0; o >>= 1)
        sump += __shfl_down_sync(0xffffffffu, sump, o);
    __shared__ double psh[8];
    if (lane == 0) psh[wid] = sump;
    __syncthreads();
    if (tid == 0) {
        double s = 0.0;
        for (int w = 0; w < 8; w++) s += psh[w];
        g_sumP[batch]  = s;
        g_len[batch]   = total;
        out_len[batch] = (float)total;
    }
}

// ---------------------------------------------------------------------------
// Gather x_down
// ---------------------------------------------------------------------------
__global__ void gather_kernel(const float* __restrict__ x, float* __restrict__ x_down)
{
    const int row   = blockIdx.x;
    const int batch = row >> 13;
    const int jj    = row & (Ln - 1);
    const int tid   = threadIdx.x;

    float4* dst = (float4*)(x_down + (size_t)row * Dn);
    if (jj < g_len[batch]) {
        const int src = g_src[row];
        const float4* s = (const float4*)(x + (size_t)(batch * Ln + src) * Dn);
        dst[tid] = s[tid];
    } else {
        dst[tid] = make_float4(0.f, 0.f, 0.f, 0.f);
    }
}

__global__ void finalize_kernel(float* __restrict__ o_loss)
{
    double sb = 0.0, sp = 0.0;
    for (int i = 0; i < Bn; i++) { sb += (double)g_len[i]; sp += g_sumP[i]; }
    const double F = sb / (double)BLn;
    const double G = sp / (double)BLn;
    const double N = 6.0;
    o_loss[0] = (float)(N / (N - 1.0) * ((N - 1.0) * F * G + (1.0 - F) * (1.0 - G)));
}

// ---------------------------------------------------------------------------
// Launch. Output layout (f32): x_down | P_down | b | p | lengths | ratio_loss
// ---------------------------------------------------------------------------
extern "C" void kernel_launch(void* const* d_in, const int* in_sizes, int n_in,
                              void* d_out, int out_size)
{
    const float* x  = (const float*)d_in[0];
    const float* Wq = (const float*)d_in[1];
    const float* Wk = (const float*)d_in[2];

    float* out    = (float*)d_out;
    float* o_xd   = out;
    float* o_P    = out + (size_t)BLn * Dn;
    float* o_b    = o_P + BLn;
    float* o_p    = o_b + BLn;
    float* o_len  = o_p + BLn;
    float* o_loss = o_len + Bn;

    cudaFuncSetAttribute(hgemm_kernel,
                         cudaFuncAttributeMaxDynamicSharedMemorySize, GEMM_SMEM);
    cudaFuncSetAttribute(scan_kernel,
                         cudaFuncAttributeMaxDynamicSharedMemorySize, 2 * Ln * 4);

    const int conv_blocks = (2 * WN4 + XN4 + 255) / 256;
    conv_all_kernel<<<conv_blocks, 256>>>(x, Wq, Wk);

    hgemm_kernel<<<dim3(8, 256, 2), 256, GEMM_SMEM>>>();

    props_kernel<<<BLn / 8, 256>>>(o_p, o_b);
    fixup_partial_kernel<<<Dn / 8, 256>>>(x, Wq, Wk);
    fixup_apply_kernel<<<1, MAXFIX>>>(o_b);
    scan_kernel<<<Bn, 256, 2 * Ln * 4>>>(o_p, o_b, o_P, o_len);
    gather_kernel<<<BLn, 256>>>(x, o_xd);
    finalize_kernel<<<1, 1>>>(o_loss);
}

// round 16
// speedup vs baseline: 1.3610x; 1.3610x over previous
#include <cuda_runtime.h>
#include <cuda_fp16.h>
#include <stdint.h>
#include <math.h>

// Problem shape (fixed)
#define Bn 4
#define Ln 8192
#define Dn 1024
#define BLn (Bn * Ln)   // 32768 tokens
#define MAXFIX 512

// ---------------------------------------------------------------------------
// Scratch (device globals)
// ---------------------------------------------------------------------------
__device__ __half g_qh[(size_t)BLn * Dn];           // 64 MB (32*q as fp16)
__device__ __half g_kh[(size_t)BLn * Dn];           // 64 MB (32*k as fp16)
__device__ __half g_xh[(size_t)BLn * Dn];           // 64 MB (x as fp16)
__device__ __half g_wh[2][(size_t)Dn * Dn];         // 4 MB  (32*Wq, 32*Wk fp16)
__device__ int    g_src[BLn];
__device__ int    g_len[Bn];
__device__ double g_sumP[Bn];
__device__ int    g_nfix;
__device__ int    g_fix[MAXFIX];
__device__ double g_fixacc[3][MAXFIX];

// ---------------------------------------------------------------------------
// helpers
// ---------------------------------------------------------------------------
__device__ __forceinline__ uint32_t cvta_shared_u32(const void* p) {
    uint32_t r;
    asm("{ .reg .u64 t; cvta.to.shared.u64 t, %1; cvt.u32.u64 %0, t; }"
        : "=r"(r) : "l"(p));
    return r;
}
#define LDMATRIX_X4(r0, r1, r2, r3, addr)                                  \
    asm volatile("ldmatrix.sync.aligned.m8n8.x4.shared.b16 {%0,%1,%2,%3}, [%4];" \
                 : "=r"(r0), "=r"(r1), "=r"(r2), "=r"(r3) : "r"(addr))
#define MMA16816(c0, c1, c2, c3, a0, a1, a2, a3, b0, b1)                   \
    asm volatile("mma.sync.aligned.m16n8k16.row.col.f32.f16.f16.f32 "      \
                 "{%0,%1,%2,%3}, {%4,%5,%6,%7}, {%8,%9}, {%0,%1,%2,%3};"   \
                 : "+f"(c0), "+f"(c1), "+f"(c2), "+f"(c3)                  \
                 : "r"(a0), "r"(a1), "r"(a2), "r"(a3), "r"(b0), "r"(b1))
#define CP_ASYNC16(saddr, gaddr)                                           \
    asm volatile("cp.async.cg.shared.global [%0], [%1], 16;"               \
                 :: "r"(saddr), "l"(gaddr))

// ---------------------------------------------------------------------------
// Fused converts: Wq, Wk -> fp16 scaled by 32; x -> fp16.
// ---------------------------------------------------------------------------
#define WN4 (Dn * Dn / 4)       // 262144
#define XN4 (BLn * Dn / 4)      // 8388608

__global__ void conv_all_kernel(const float* __restrict__ x,
                                const float* __restrict__ Wq,
                                const float* __restrict__ Wk)
{
    const int i = blockIdx.x * blockDim.x + threadIdx.x;
    if (i == 0) g_nfix = 0;     // reset fixup list each replay

    if (i < 2 * WN4) {
        const int which = i >> 18;            // 0: Wq, 1: Wk
        const int jj    = i & (WN4 - 1);
        const float4 v = ((const float4*)(which ? Wk : Wq))[jj];
        const __half2 h0 = __floats2half2_rn(32.0f * v.x, 32.0f * v.y);
        const __half2 h1 = __floats2half2_rn(32.0f * v.z, 32.0f * v.w);
        uint2 u;
        u.x = *(const uint32_t*)&h0;
        u.y = *(const uint32_t*)&h1;
        ((uint2*)&g_wh[which][0])[jj] = u;
    } else {
        const int jj = i - 2 * WN4;
        if (jj < XN4) {
            const float4 v = ((const float4*)x)[jj];
            const __half2 h0 = __floats2half2_rn(v.x, v.y);
            const __half2 h1 = __floats2half2_rn(v.z, v.w);
            uint2 u;
            u.x = *(const uint32_t*)&h0;
            u.y = *(const uint32_t*)&h1;
            ((uint2*)&g_xh[0])[jj] = u;
        }
    }
}

// ---------------------------------------------------------------------------
// HMMA fp16 GEMM (single product): C = X * W^T, C stored as fp16.
// Tile 128x128, BK=64 (128B rows, XOR swizzle), 256 threads (8 warps 2x4),
// warp tile 64x32.  2 smem buffers, loads issued then wait_group 1 (R13).
// grid = (8 n-tiles, 256 m-tiles, 2 gemms).
// ---------------------------------------------------------------------------
#define SIDE_BYTES  16384                  // 128 rows * 128 B
#define BUF_BYTES   (2 * SIDE_BYTES)       // 32768 (A side + B side)
#define GEMM_SMEM   (2 * BUF_BYTES)        // 65536

// swizzled byte offset of 16B unit u (0..7) in row r (128B rows)
__device__ __forceinline__ uint32_t sw_off(int r, int u) {
    return (uint32_t)(128 * r + 16 * (u ^ (r & 7)));
}

__global__ __launch_bounds__(256, 2)
void hgemm_kernel()
{
    extern __shared__ char smem[];
    const uint32_t sbase = cvta_shared_u32(smem);

    const int tid  = threadIdx.x;
    const int wid  = tid >> 5;
    const int lane = tid & 31;
    const int wm   = wid & 1;          // 0..1 : 64-row half
    const int wn   = wid >> 1;         // 0..3 : 32-col quarter
    const int tn = blockIdx.x, tm = blockIdx.y, gz = blockIdx.z;

    const int j    = lane >> 3;        // ldmatrix matrix id 0..3
    const int rlow = lane & 7;

    int rA[4], rB[2];
    #pragma unroll
    for (int mt = 0; mt < 4; mt++)
        rA[mt] = wm * 64 + mt * 16 + (j & 1) * 8 + rlow;
    #pragma unroll
    for (int g = 0; g < 2; g++)
        rB[g] = wn * 32 + g * 16 + (j & 1) * 8 + rlow;
    const int jhi = j >> 1;

    float acc[4][4][4];
    #pragma unroll
    for (int mt = 0; mt < 4; mt++)
        #pragma unroll
        for (int nt = 0; nt < 4; nt++)
            #pragma unroll
            for (int e = 0; e < 4; e++) acc[mt][nt][e] = 0.0f;

    const char* xbase = (const char*)&g_xh[0] + (size_t)(tm * 128) * (Dn * 2);
    const char* wbase = (const char*)&g_wh[gz][0] + (size_t)(tn * 128) * (Dn * 2);

    // loader: 8 x 16B units per thread per chunk (2048 units total)
    int l_side[8], l_r[8], l_u[8];
    #pragma unroll
    for (int i = 0; i < 8; i++) {
        const int v    = tid + i * 256;
        const int side = v >= 1024;
        const int w    = v & 1023;
        l_side[i] = side;
        l_r[i]    = w >> 3;
        l_u[i]    = w & 7;
    }

    #define LOAD_CHUNK(buf, c)                                                   \
    do {                                                                         \
        const uint32_t bb = sbase + (buf) * BUF_BYTES;                           \
        _Pragma("unroll")                                                        \
        for (int i = 0; i < 8; i++) {                                            \
            const uint32_t sa = bb + l_side[i] * SIDE_BYTES +                    \
                                sw_off(l_r[i], l_u[i]);                          \
            const char* ga = (l_side[i] ? wbase : xbase) +                       \
                             (size_t)l_r[i] * (Dn * 2) + (c) * 128 + l_u[i] * 16;\
            CP_ASYNC16(sa, ga);                                                  \
        }                                                                        \
        asm volatile("cp.async.commit_group;");                                  \
    } while (0)

    const int NCH = Dn / 64;   // 16 chunks
    LOAD_CHUNK(0, 0);

    for (int c = 0; c < NCH; c++) {
        const int buf = c & 1;
        if (c + 1 < NCH) {
            LOAD_CHUNK(buf ^ 1, c + 1);
            asm volatile("cp.async.wait_group 1;");
        } else {
            asm volatile("cp.async.wait_group 0;");
        }
        __syncthreads();

        const uint32_t aB = sbase + buf * BUF_BYTES;
        const uint32_t bB = aB + SIDE_BYTES;

        #pragma unroll
        for (int ks = 0; ks < 4; ks++) {
            uint32_t bfr[4][2];
            #pragma unroll
            for (int g = 0; g < 2; g++) {
                uint32_t r0, r1, r2, r3;
                const uint32_t addr = bB + 128 * rB[g] +
                    16 * ((2 * ks + jhi) ^ (rB[g] & 7));
                LDMATRIX_X4(r0, r1, r2, r3, addr);
                bfr[2 * g + 0][0] = r0; bfr[2 * g + 0][1] = r2;
                bfr[2 * g + 1][0] = r1; bfr[2 * g + 1][1] = r3;
            }
            uint32_t afr[4][4];
            #pragma unroll
            for (int mt = 0; mt < 4; mt++) {
                const uint32_t addr = aB + 128 * rA[mt] +
                    16 * ((2 * ks + jhi) ^ (rA[mt] & 7));
                LDMATRIX_X4(afr[mt][0], afr[mt][1], afr[mt][2], afr[mt][3], addr);
            }
            #pragma unroll
            for (int mt = 0; mt < 4; mt++)
                #pragma unroll
                for (int nt = 0; nt < 4; nt++)
                    MMA16816(acc[mt][nt][0], acc[mt][nt][1],
                             acc[mt][nt][2], acc[mt][nt][3],
                             afr[mt][0], afr[mt][1], afr[mt][2], afr[mt][3],
                             bfr[nt][0], bfr[nt][1]);
        }
        __syncthreads();
    }

    // epilogue: store as fp16 (values are 32x true q/k; cos is scale-inv)
    __half* C = (gz == 0) ? g_qh : g_kh;
    const int rowb = tm * 128 + wm * 64 + (lane >> 2);
    const int colb = tn * 128 + wn * 32 + 2 * (lane & 3);
    #pragma unroll
    for (int mt = 0; mt < 4; mt++) {
        #pragma unroll
        for (int nt = 0; nt < 4; nt++) {
            const size_t r0 = (size_t)(rowb + mt * 16) * Dn + colb + nt * 8;
            const __half2 lo = __floats2half2_rn(acc[mt][nt][0], acc[mt][nt][1]);
            const __half2 hi = __floats2half2_rn(acc[mt][nt][2], acc[mt][nt][3]);
            *(__half2*)&C[r0]          = lo;
            *(__half2*)&C[r0 + 8 * Dn] = hi;
        }
    }
    #undef LOAD_CHUNK
}

// ---------------------------------------------------------------------------
// Per-token props: warp per token, fp16 q/k reads, fp32 math, shfl-only.
// ---------------------------------------------------------------------------
__global__ void props_kernel(float* __restrict__ out_p, float* __restrict__ out_b)
{
    const int t    = blockIdx.x * 8 + (threadIdx.x >> 5);
    const int lane = threadIdx.x & 31;

    if ((t & (Ln - 1)) == 0) {
        if (lane == 0) { out_p[t] = 1.0f; out_b[t] = 1.0f; }
        return;
    }
    const uint4* qr = (const uint4*)(g_qh + (size_t)t * Dn);
    const uint4* kr = (const uint4*)(g_kh + (size_t)(t - 1) * Dn);

    float sq = 0.f, sk = 0.f, sp = 0.f;
    #pragma unroll
    for (int i = 0; i < 4; i++) {
        const uint4 qu = qr[lane + i * 32];
        const uint4 ku = kr[lane + i * 32];
        const uint32_t qa[4] = {qu.x, qu.y, qu.z, qu.w};
        const uint32_t ka[4] = {ku.x, ku.y, ku.z, ku.w};
        #pragma unroll
        for (int c = 0; c < 4; c++) {
            const float2 qf = __half22float2(*(const __half2*)&qa[c]);
            const float2 kf = __half22float2(*(const __half2*)&ka[c]);
            sq = fmaf(qf.x, qf.x, sq); sq = fmaf(qf.y, qf.y, sq);
            sk = fmaf(kf.x, kf.x, sk); sk = fmaf(kf.y, kf.y, sk);
            sp = fmaf(qf.x, kf.x, sp); sp = fmaf(qf.y, kf.y, sp);
        }
    }
    #pragma unroll
    for (int o = 16; o > 0; o >>= 1) {
        sq += __shfl_down_sync(0xffffffffu, sq, o);
        sk += __shfl_down_sync(0xffffffffu, sk, o);
        sp += __shfl_down_sync(0xffffffffu, sp, o);
    }
    if (lane == 0) {
        const float nq = fmaxf(sqrtf(sq), 1e-12f);
        const float nk = fmaxf(sqrtf(sk), 1e-12f);
        const float cs = sp / (nq * nk);
        const float pv = 0.5f * (1.0f - cs);
        out_p[t] = pv;
        out_b[t] = (pv >= 0.5f) ? 1.0f : 0.0f;
        if (fabsf(cs) < 1e-4f) {
            const int ix = atomicAdd(&g_nfix, 1);
            if (ix < MAXFIX) {
                g_fix[ix] = t;
                g_fixacc[0][ix] = 0.0;
                g_fixacc[1][ix] = 0.0;
                g_fixacc[2][ix] = 0.0;
            }
        }
    }
}

// ---------------------------------------------------------------------------
// Fixup stage 1: exact partial sums for flagged tokens.
// grid = (64 e-slices of 16 rows, ceil(MAXFIX/4) token groups), 256 threads.
// Each block stages 4 tokens' x rows in smem and sweeps its 128KB W-slice;
// tokens 2-4 hit L1.  Row dots fp32; squares accumulated in fp64.
// ---------------------------------------------------------------------------
__global__ __launch_bounds__(256)
void fixup_partial_kernel(const float* __restrict__ x,
                          const float* __restrict__ Wq,
                          const float* __restrict__ Wk)
{
    const int nf = (g_nfix < MAXFIX) ? g_nfix : MAXFIX;
    const int g0 = blockIdx.y * 4;
    if (g0 >= nf) return;
    const int ntok = (nf - g0 < 4) ? (nf - g0) : 4;
    const int sl   = blockIdx.x;            // e-slice: 16 rows
    const int tid  = threadIdx.x;
    const int lane = tid & 31, wrp = tid >> 5;

    __shared__ float xs[4][Dn], xp[4][Dn];  // 32 KB
    for (int tt = 0; tt < ntok; tt++) {
        const int t = g_fix[g0 + tt];
        for (int d = tid; d < Dn; d += 256) {
            xs[tt][d] = x[(size_t)t * Dn + d];
            xp[tt][d] = x[(size_t)(t - 1) * Dn + d];
        }
    }
    __syncthreads();

    for (int tt = 0; tt < ntok; tt++) {
        double sq = 0.0, sk = 0.0, sp = 0.0;
        #pragma unroll
        for (int i = 0; i < 2; i++) {
            const int e = sl * 16 + wrp * 2 + i;
            const float4* wq = (const float4*)(Wq + (size_t)e * Dn);
            const float4* wk = (const float4*)(Wk + (size_t)e * Dn);
            float qd = 0.f, kd = 0.f;
            #pragma unroll
            for (int jj = 0; jj < 8; jj++) {
                const int d4 = lane + jj * 32;
                const float4 w4 = wq[d4];
                const float4 v4 = wk[d4];
                const float4 a4 = *(const float4*)&xs[tt][d4 * 4];
                const float4 b4 = *(const float4*)&xp[tt][d4 * 4];
                qd = fmaf(a4.x, w4.x, qd); qd = fmaf(a4.y, w4.y, qd);
                qd = fmaf(a4.z, w4.z, qd); qd = fmaf(a4.w, w4.w, qd);
                kd = fmaf(b4.x, v4.x, kd); kd = fmaf(b4.y, v4.y, kd);
                kd = fmaf(b4.z, v4.z, kd); kd = fmaf(b4.w, v4.w, kd);
            }
            #pragma unroll
            for (int o = 16; o > 0; o >>= 1) {
                qd += __shfl_down_sync(0xffffffffu, qd, o);
                kd += __shfl_down_sync(0xffffffffu, kd, o);
            }
            if (lane == 0) {
                sq += (double)qd * qd;
                sk += (double)kd * kd;
                sp += (double)qd * kd;
            }
        }
        if (lane == 0) {
            atomicAdd(&g_fixacc[0][g0 + tt], sq);
            atomicAdd(&g_fixacc[1][g0 + tt], sk);
            atomicAdd(&g_fixacc[2][g0 + tt], sp);
        }
    }
}

// Fixup stage 2: decide b from the exact sums.
__global__ void fixup_apply_kernel(float* __restrict__ out_b)
{
    const int i = threadIdx.x;
    const int nf = (g_nfix < MAXFIX) ? g_nfix : MAXFIX;
    if (i < nf) {
        const double cs = g_fixacc[2][i] / sqrt(g_fixacc[0][i] * g_fixacc[1][i]);
        out_b[g_fix[i]] = (cs <= 0.0) ? 1.0f : 0.0f;
    }
}

// ---------------------------------------------------------------------------
// Per-batch scan of b — b/p staged through smem with coalesced loads.
// ---------------------------------------------------------------------------
__global__ void scan_kernel(const float* __restrict__ p_arr,
                            const float* __restrict__ b_arr,
                            float* __restrict__ P_down,
                            float* __restrict__ out_len)
{
    extern __shared__ float sc[];           // [0,Ln): b, [Ln,2Ln): p
    float* sb = sc;
    float* sp_ = sc + Ln;

    const int batch = blockIdx.x;
    const int tid   = threadIdx.x;
    const float4* bb4 = (const float4*)(b_arr + batch * Ln);
    const float4* pp4 = (const float4*)(p_arr + batch * Ln);
    #pragma unroll
    for (int i = 0; i < Ln / 4 / 256; i++) {
        const int idx = tid + i * 256;
        *(float4*)&sb[idx * 4]  = bb4[idx];
        *(float4*)&sp_[idx * 4] = pp4[idx];
    }
    __syncthreads();

    const int base = tid * 32;
    int    cnt  = 0;
    double sump = 0.0;
    #pragma unroll 8
    for (int jj = 0; jj < 32; jj++) {
        cnt  += (sb[base + jj] > 0.5f) ? 1 : 0;
        sump += (double)sp_[base + jj];
    }
    const int lane = tid & 31, wid = tid >> 5;
    int v = cnt;
    #pragma unroll
    for (int o = 1; o < 32; o <<= 1) {
        const int n = __shfl_up_sync(0xffffffffu, v, o);
        if (lane >= o) v += n;
    }
    __shared__ int wsum[8], woff[8], stotal;
    if (lane == 31) wsum[wid] = v;
    __syncthreads();
    if (tid == 0) {
        int s = 0;
        for (int w = 0; w < 8; w++) { woff[w] = s; s += wsum[w]; }
        stotal = s;
    }
    __syncthreads();

    int slot = woff[wid] + v - cnt;
    const int total = stotal;

    for (int jj = 0; jj < 32; jj++) {
        if (sb[base + jj] > 0.5f) {
            const int l = base + jj;
            g_src[batch * Ln + slot]  = l;
            P_down[batch * Ln + slot] = sp_[l];
            slot++;
        }
    }
    for (int s = total + tid; s < Ln; s += 256)
        P_down[batch * Ln + s] = 0.0f;

    #pragma unroll
    for (int o = 16; o > 0; o >>= 1)
        sump += __shfl_down_sync(0xffffffffu, sump, o);
    __shared__ double psh[8];
    if (lane == 0) psh[wid] = sump;
    __syncthreads();
    if (tid == 0) {
        double s = 0.0;
        for (int w = 0; w < 8; w++) s += psh[w];
        g_sumP[batch]  = s;
        g_len[batch]   = total;
        out_len[batch] = (float)total;
    }
}

// ---------------------------------------------------------------------------
// Gather x_down
// ---------------------------------------------------------------------------
__global__ void gather_kernel(const float* __restrict__ x, float* __restrict__ x_down)
{
    const int row   = blockIdx.x;
    const int batch = row >> 13;
    const int jj    = row & (Ln - 1);
    const int tid   = threadIdx.x;

    float4* dst = (float4*)(x_down + (size_t)row * Dn);
    if (jj < g_len[batch]) {
        const int src = g_src[row];
        const float4* s = (const float4*)(x + (size_t)(batch * Ln + src) * Dn);
        dst[tid] = s[tid];
    } else {
        dst[tid] = make_float4(0.f, 0.f, 0.f, 0.f);
    }
}

__global__ void finalize_kernel(float* __restrict__ o_loss)
{
    double sb = 0.0, sp = 0.0;
    for (int i = 0; i < Bn; i++) { sb += (double)g_len[i]; sp += g_sumP[i]; }
    const double F = sb / (double)BLn;
    const double G = sp / (double)BLn;
    const double N = 6.0;
    o_loss[0] = (float)(N / (N - 1.0) * ((N - 1.0) * F * G + (1.0 - F) * (1.0 - G)));
}

// ---------------------------------------------------------------------------
// Launch. Output layout (f32): x_down | P_down | b | p | lengths | ratio_loss
// ---------------------------------------------------------------------------
extern "C" void kernel_launch(void* const* d_in, const int* in_sizes, int n_in,
                              void* d_out, int out_size)
{
    const float* x  = (const float*)d_in[0];
    const float* Wq = (const float*)d_in[1];
    const float* Wk = (const float*)d_in[2];

    float* out    = (float*)d_out;
    float* o_xd   = out;
    float* o_P    = out + (size_t)BLn * Dn;
    float* o_b    = o_P + BLn;
    float* o_p    = o_b + BLn;
    float* o_len  = o_p + BLn;
    float* o_loss = o_len + Bn;

    cudaFuncSetAttribute(hgemm_kernel,
                         cudaFuncAttributeMaxDynamicSharedMemorySize, GEMM_SMEM);
    cudaFuncSetAttribute(scan_kernel,
                         cudaFuncAttributeMaxDynamicSharedMemorySize, 2 * Ln * 4);

    const int conv_blocks = (2 * WN4 + XN4 + 255) / 256;
    conv_all_kernel<<<conv_blocks, 256>>>(x, Wq, Wk);

    hgemm_kernel<<<dim3(8, 256, 2), 256, GEMM_SMEM>>>();

    props_kernel<<<BLn / 8, 256>>>(o_p, o_b);
    fixup_partial_kernel<<<dim3(64, MAXFIX / 4), 256>>>(x, Wq, Wk);
    fixup_apply_kernel<<<1, MAXFIX>>>(o_b);
    scan_kernel<<<Bn, 256, 2 * Ln * 4>>>(o_p, o_b, o_P, o_len);
    gather_kernel<<<BLn, 256>>>(x, o_xd);
    finalize_kernel<<<1, 1>>>(o_loss);
}

// round 17
// speedup vs baseline: 1.5734x; 1.1560x over previous
#include <cuda_runtime.h>
#include <cuda_fp16.h>
#include <stdint.h>
#include <math.h>

// Problem shape (fixed)
#define Bn 4
#define Ln 8192
#define Dn 1024
#define BLn (Bn * Ln)   // 32768 tokens
#define MAXFIX 512

// ---------------------------------------------------------------------------
// Scratch (device globals)
// ---------------------------------------------------------------------------
__device__ __half g_qh[(size_t)BLn * Dn];           // 64 MB (32*q as fp16)
__device__ __half g_kh[(size_t)BLn * Dn];           // 64 MB (32*k as fp16)
__device__ __half g_xh[(size_t)BLn * Dn];           // 64 MB (x as fp16)
__device__ __half g_wh[2][(size_t)Dn * Dn];         // 4 MB  (32*Wq, 32*Wk fp16)
__device__ int    g_src[BLn];
__device__ int    g_len[Bn];
__device__ double g_sumP[Bn];
__device__ int    g_nfix;
__device__ int    g_fix[MAXFIX];
__device__ double g_fixacc[3][MAXFIX];

// ---------------------------------------------------------------------------
// helpers
// ---------------------------------------------------------------------------
__device__ __forceinline__ uint32_t cvta_shared_u32(const void* p) {
    uint32_t r;
    asm("{ .reg .u64 t; cvta.to.shared.u64 t, %1; cvt.u32.u64 %0, t; }"
        : "=r"(r) : "l"(p));
    return r;
}
#define LDMATRIX_X4(r0, r1, r2, r3, addr)                                  \
    asm volatile("ldmatrix.sync.aligned.m8n8.x4.shared.b16 {%0,%1,%2,%3}, [%4];" \
                 : "=r"(r0), "=r"(r1), "=r"(r2), "=r"(r3) : "r"(addr))
#define MMA16816(c0, c1, c2, c3, a0, a1, a2, a3, b0, b1)                   \
    asm volatile("mma.sync.aligned.m16n8k16.row.col.f32.f16.f16.f32 "      \
                 "{%0,%1,%2,%3}, {%4,%5,%6,%7}, {%8,%9}, {%0,%1,%2,%3};"   \
                 : "+f"(c0), "+f"(c1), "+f"(c2), "+f"(c3)                  \
                 : "r"(a0), "r"(a1), "r"(a2), "r"(a3), "r"(b0), "r"(b1))
#define CP_ASYNC16(saddr, gaddr)                                           \
    asm volatile("cp.async.cg.shared.global [%0], [%1], 16;"               \
                 :: "r"(saddr), "l"(gaddr))

// ---------------------------------------------------------------------------
// Fused converts: Wq, Wk -> fp16 scaled by 32; x -> fp16.
// ---------------------------------------------------------------------------
#define WN4 (Dn * Dn / 4)       // 262144
#define XN4 (BLn * Dn / 4)      // 8388608

__global__ void conv_all_kernel(const float* __restrict__ x,
                                const float* __restrict__ Wq,
                                const float* __restrict__ Wk)
{
    const int i = blockIdx.x * blockDim.x + threadIdx.x;
    if (i == 0) g_nfix = 0;     // reset fixup list each replay

    if (i < 2 * WN4) {
        const int which = i >> 18;            // 0: Wq, 1: Wk
        const int jj    = i & (WN4 - 1);
        const float4 v = ((const float4*)(which ? Wk : Wq))[jj];
        const __half2 h0 = __floats2half2_rn(32.0f * v.x, 32.0f * v.y);
        const __half2 h1 = __floats2half2_rn(32.0f * v.z, 32.0f * v.w);
        uint2 u;
        u.x = *(const uint32_t*)&h0;
        u.y = *(const uint32_t*)&h1;
        ((uint2*)&g_wh[which][0])[jj] = u;
    } else {
        const int jj = i - 2 * WN4;
        if (jj < XN4) {
            const float4 v = ((const float4*)x)[jj];
            const __half2 h0 = __floats2half2_rn(v.x, v.y);
            const __half2 h1 = __floats2half2_rn(v.z, v.w);
            uint2 u;
            u.x = *(const uint32_t*)&h0;
            u.y = *(const uint32_t*)&h1;
            ((uint2*)&g_xh[0])[jj] = u;
        }
    }
}

// ---------------------------------------------------------------------------
// HMMA fp16 GEMM (single product): C = X * W^T, C stored as fp16.
// Tile 128x128, BK=64 (128B rows, XOR swizzle), 256 threads (8 warps 2x4),
// warp tile 64x32.  2 smem buffers, loads issued then wait_group 1.
// grid = (8 n-tiles, 256 m-tiles, 2 gemms).
// ---------------------------------------------------------------------------
#define SIDE_BYTES  16384                  // 128 rows * 128 B
#define BUF_BYTES   (2 * SIDE_BYTES)       // 32768 (A side + B side)
#define GEMM_SMEM   (2 * BUF_BYTES)        // 65536

// swizzled byte offset of 16B unit u (0..7) in row r (128B rows)
__device__ __forceinline__ uint32_t sw_off(int r, int u) {
    return (uint32_t)(128 * r + 16 * (u ^ (r & 7)));
}

__global__ __launch_bounds__(256, 2)
void hgemm_kernel()
{
    extern __shared__ char smem[];
    const uint32_t sbase = cvta_shared_u32(smem);

    const int tid  = threadIdx.x;
    const int wid  = tid >> 5;
    const int lane = tid & 31;
    const int wm   = wid & 1;          // 0..1 : 64-row half
    const int wn   = wid >> 1;         // 0..3 : 32-col quarter
    const int tn = blockIdx.x, tm = blockIdx.y, gz = blockIdx.z;

    const int j    = lane >> 3;        // ldmatrix matrix id 0..3
    const int rlow = lane & 7;

    int rA[4], rB[2];
    #pragma unroll
    for (int mt = 0; mt < 4; mt++)
        rA[mt] = wm * 64 + mt * 16 + (j & 1) * 8 + rlow;
    #pragma unroll
    for (int g = 0; g < 2; g++)
        rB[g] = wn * 32 + g * 16 + (j & 1) * 8 + rlow;
    const int jhi = j >> 1;

    float acc[4][4][4];
    #pragma unroll
    for (int mt = 0; mt < 4; mt++)
        #pragma unroll
        for (int nt = 0; nt < 4; nt++)
            #pragma unroll
            for (int e = 0; e < 4; e++) acc[mt][nt][e] = 0.0f;

    const char* xbase = (const char*)&g_xh[0] + (size_t)(tm * 128) * (Dn * 2);
    const char* wbase = (const char*)&g_wh[gz][0] + (size_t)(tn * 128) * (Dn * 2);

    // loader: 8 x 16B units per thread per chunk (2048 units total)
    int l_side[8], l_r[8], l_u[8];
    #pragma unroll
    for (int i = 0; i < 8; i++) {
        const int v    = tid + i * 256;
        const int side = v >= 1024;
        const int w    = v & 1023;
        l_side[i] = side;
        l_r[i]    = w >> 3;
        l_u[i]    = w & 7;
    }

    #define LOAD_CHUNK(buf, c)                                                   \
    do {                                                                         \
        const uint32_t bb = sbase + (buf) * BUF_BYTES;                           \
        _Pragma("unroll")                                                        \
        for (int i = 0; i < 8; i++) {                                            \
            const uint32_t sa = bb + l_side[i] * SIDE_BYTES +                    \
                                sw_off(l_r[i], l_u[i]);                          \
            const char* ga = (l_side[i] ? wbase : xbase) +                       \
                             (size_t)l_r[i] * (Dn * 2) + (c) * 128 + l_u[i] * 16;\
            CP_ASYNC16(sa, ga);                                                  \
        }                                                                        \
        asm volatile("cp.async.commit_group;");                                  \
    } while (0)

    const int NCH = Dn / 64;   // 16 chunks
    LOAD_CHUNK(0, 0);

    for (int c = 0; c < NCH; c++) {
        const int buf = c & 1;
        if (c + 1 < NCH) {
            LOAD_CHUNK(buf ^ 1, c + 1);
            asm volatile("cp.async.wait_group 1;");
        } else {
            asm volatile("cp.async.wait_group 0;");
        }
        __syncthreads();

        const uint32_t aB = sbase + buf * BUF_BYTES;
        const uint32_t bB = aB + SIDE_BYTES;

        #pragma unroll
        for (int ks = 0; ks < 4; ks++) {
            uint32_t bfr[4][2];
            #pragma unroll
            for (int g = 0; g < 2; g++) {
                uint32_t r0, r1, r2, r3;
                const uint32_t addr = bB + 128 * rB[g] +
                    16 * ((2 * ks + jhi) ^ (rB[g] & 7));
                LDMATRIX_X4(r0, r1, r2, r3, addr);
                bfr[2 * g + 0][0] = r0; bfr[2 * g + 0][1] = r2;
                bfr[2 * g + 1][0] = r1; bfr[2 * g + 1][1] = r3;
            }
            uint32_t afr[4][4];
            #pragma unroll
            for (int mt = 0; mt < 4; mt++) {
                const uint32_t addr = aB + 128 * rA[mt] +
                    16 * ((2 * ks + jhi) ^ (rA[mt] & 7));
                LDMATRIX_X4(afr[mt][0], afr[mt][1], afr[mt][2], afr[mt][3], addr);
            }
            #pragma unroll
            for (int mt = 0; mt < 4; mt++)
                #pragma unroll
                for (int nt = 0; nt < 4; nt++)
                    MMA16816(acc[mt][nt][0], acc[mt][nt][1],
                             acc[mt][nt][2], acc[mt][nt][3],
                             afr[mt][0], afr[mt][1], afr[mt][2], afr[mt][3],
                             bfr[nt][0], bfr[nt][1]);
        }
        __syncthreads();
    }

    // epilogue: store as fp16 (values are 32x true q/k; cos is scale-inv)
    __half* C = (gz == 0) ? g_qh : g_kh;
    const int rowb = tm * 128 + wm * 64 + (lane >> 2);
    const int colb = tn * 128 + wn * 32 + 2 * (lane & 3);
    #pragma unroll
    for (int mt = 0; mt < 4; mt++) {
        #pragma unroll
        for (int nt = 0; nt < 4; nt++) {
            const size_t r0 = (size_t)(rowb + mt * 16) * Dn + colb + nt * 8;
            const __half2 lo = __floats2half2_rn(acc[mt][nt][0], acc[mt][nt][1]);
            const __half2 hi = __floats2half2_rn(acc[mt][nt][2], acc[mt][nt][3]);
            *(__half2*)&C[r0]          = lo;
            *(__half2*)&C[r0 + 8 * Dn] = hi;
        }
    }
    #undef LOAD_CHUNK
}

// ---------------------------------------------------------------------------
// Per-token props: warp per token, fp16 q/k reads, fp32 math, shfl-only.
// Flag |cos| < 4e-5 (~3.6 sigma of the fp16-path cos error) for exact fixup.
// ---------------------------------------------------------------------------
__global__ void props_kernel(float* __restrict__ out_p, float* __restrict__ out_b)
{
    const int t    = blockIdx.x * 8 + (threadIdx.x >> 5);
    const int lane = threadIdx.x & 31;

    if ((t & (Ln - 1)) == 0) {
        if (lane == 0) { out_p[t] = 1.0f; out_b[t] = 1.0f; }
        return;
    }
    const uint4* qr = (const uint4*)(g_qh + (size_t)t * Dn);
    const uint4* kr = (const uint4*)(g_kh + (size_t)(t - 1) * Dn);

    float sq = 0.f, sk = 0.f, sp = 0.f;
    #pragma unroll
    for (int i = 0; i < 4; i++) {
        const uint4 qu = qr[lane + i * 32];
        const uint4 ku = kr[lane + i * 32];
        const uint32_t qa[4] = {qu.x, qu.y, qu.z, qu.w};
        const uint32_t ka[4] = {ku.x, ku.y, ku.z, ku.w};
        #pragma unroll
        for (int c = 0; c < 4; c++) {
            const float2 qf = __half22float2(*(const __half2*)&qa[c]);
            const float2 kf = __half22float2(*(const __half2*)&ka[c]);
            sq = fmaf(qf.x, qf.x, sq); sq = fmaf(qf.y, qf.y, sq);
            sk = fmaf(kf.x, kf.x, sk); sk = fmaf(kf.y, kf.y, sk);
            sp = fmaf(qf.x, kf.x, sp); sp = fmaf(qf.y, kf.y, sp);
        }
    }
    #pragma unroll
    for (int o = 16; o > 0; o >>= 1) {
        sq += __shfl_down_sync(0xffffffffu, sq, o);
        sk += __shfl_down_sync(0xffffffffu, sk, o);
        sp += __shfl_down_sync(0xffffffffu, sp, o);
    }
    if (lane == 0) {
        const float nq = fmaxf(sqrtf(sq), 1e-12f);
        const float nk = fmaxf(sqrtf(sk), 1e-12f);
        const float cs = sp / (nq * nk);
        const float pv = 0.5f * (1.0f - cs);
        out_p[t] = pv;
        out_b[t] = (pv >= 0.5f) ? 1.0f : 0.0f;
        if (fabsf(cs) < 4e-5f) {
            const int ix = atomicAdd(&g_nfix, 1);
            if (ix < MAXFIX) {
                g_fix[ix] = t;
                g_fixacc[0][ix] = 0.0;
                g_fixacc[1][ix] = 0.0;
                g_fixacc[2][ix] = 0.0;
            }
        }
    }
}

// ---------------------------------------------------------------------------
// Fixup stage 1: exact partial sums for flagged tokens.
// grid = (32 e-slices, MAXFIX token slots), 256 threads; 4 rows per warp.
// Row dots in fp32 (error ~3e-8 at cos level); squares accumulated in fp64.
// ---------------------------------------------------------------------------
__global__ void fixup_partial_kernel(const float* __restrict__ x,
                                     const float* __restrict__ Wq,
                                     const float* __restrict__ Wk)
{
    const int nf = (g_nfix < MAXFIX) ? g_nfix : MAXFIX;
    const int it = blockIdx.y;
    if (it >= nf) return;
    const int t  = g_fix[it];
    const int sl = blockIdx.x;              // e-slice: 32 rows
    const int tid = threadIdx.x;
    const int lane = tid & 31, wrp = tid >> 5;

    __shared__ float xs[Dn], xp[Dn];
    for (int d = tid; d < Dn; d += 256) {
        xs[d] = x[(size_t)t * Dn + d];
        xp[d] = x[(size_t)(t - 1) * Dn + d];
    }
    __syncthreads();

    double sq = 0.0, sk = 0.0, sp = 0.0;
    #pragma unroll
    for (int i = 0; i < 4; i++) {
        const int e = sl * 32 + wrp * 4 + i;
        const float4* wq = (const float4*)(Wq + (size_t)e * Dn);
        const float4* wk = (const float4*)(Wk + (size_t)e * Dn);
        float qd = 0.f, kd = 0.f;
        #pragma unroll
        for (int jj = 0; jj < 8; jj++) {
            const int d4 = lane + jj * 32;
            const float4 w4 = wq[d4];
            const float4 v4 = wk[d4];
            const float4 a4 = *(const float4*)&xs[d4 * 4];
            const float4 b4 = *(const float4*)&xp[d4 * 4];
            qd = fmaf(a4.x, w4.x, qd); qd = fmaf(a4.y, w4.y, qd);
            qd = fmaf(a4.z, w4.z, qd); qd = fmaf(a4.w, w4.w, qd);
            kd = fmaf(b4.x, v4.x, kd); kd = fmaf(b4.y, v4.y, kd);
            kd = fmaf(b4.z, v4.z, kd); kd = fmaf(b4.w, v4.w, kd);
        }
        #pragma unroll
        for (int o = 16; o > 0; o >>= 1) {
            qd += __shfl_down_sync(0xffffffffu, qd, o);
            kd += __shfl_down_sync(0xffffffffu, kd, o);
        }
        if (lane == 0) {
            sq += (double)qd * qd;
            sk += (double)kd * kd;
            sp += (double)qd * kd;
        }
    }
    if (lane == 0) {
        atomicAdd(&g_fixacc[0][it], sq);
        atomicAdd(&g_fixacc[1][it], sk);
        atomicAdd(&g_fixacc[2][it], sp);
    }
}

// Fixup stage 2: decide b from the exact sums.
__global__ void fixup_apply_kernel(float* __restrict__ out_b)
{
    const int i = threadIdx.x;
    const int nf = (g_nfix < MAXFIX) ? g_nfix : MAXFIX;
    if (i < nf) {
        const double cs = g_fixacc[2][i] / sqrt(g_fixacc[0][i] * g_fixacc[1][i]);
        out_b[g_fix[i]] = (cs <= 0.0) ? 1.0f : 0.0f;
    }
}

// ---------------------------------------------------------------------------
// Per-batch scan of b — b/p staged through smem with coalesced loads.
// ---------------------------------------------------------------------------
__global__ void scan_kernel(const float* __restrict__ p_arr,
                            const float* __restrict__ b_arr,
                            float* __restrict__ P_down,
                            float* __restrict__ out_len)
{
    extern __shared__ float sc[];           // [0,Ln): b, [Ln,2Ln): p
    float* sb = sc;
    float* sp_ = sc + Ln;

    const int batch = blockIdx.x;
    const int tid   = threadIdx.x;
    const float4* bb4 = (const float4*)(b_arr + batch * Ln);
    const float4* pp4 = (const float4*)(p_arr + batch * Ln);
    #pragma unroll
    for (int i = 0; i < Ln / 4 / 256; i++) {
        const int idx = tid + i * 256;
        *(float4*)&sb[idx * 4]  = bb4[idx];
        *(float4*)&sp_[idx * 4] = pp4[idx];
    }
    __syncthreads();

    const int base = tid * 32;
    int    cnt  = 0;
    double sump = 0.0;
    #pragma unroll 8
    for (int jj = 0; jj < 32; jj++) {
        cnt  += (sb[base + jj] > 0.5f) ? 1 : 0;
        sump += (double)sp_[base + jj];
    }
    const int lane = tid & 31, wid = tid >> 5;
    int v = cnt;
    #pragma unroll
    for (int o = 1; o < 32; o <<= 1) {
        const int n = __shfl_up_sync(0xffffffffu, v, o);
        if (lane >= o) v += n;
    }
    __shared__ int wsum[8], woff[8], stotal;
    if (lane == 31) wsum[wid] = v;
    __syncthreads();
    if (tid == 0) {
        int s = 0;
        for (int w = 0; w < 8; w++) { woff[w] = s; s += wsum[w]; }
        stotal = s;
    }
    __syncthreads();

    int slot = woff[wid] + v - cnt;
    const int total = stotal;

    for (int jj = 0; jj < 32; jj++) {
        if (sb[base + jj] > 0.5f) {
            const int l = base + jj;
            g_src[batch * Ln + slot]  = l;
            P_down[batch * Ln + slot] = sp_[l];
            slot++;
        }
    }
    for (int s = total + tid; s < Ln; s += 256)
        P_down[batch * Ln + s] = 0.0f;

    #pragma unroll
    for (int o = 16; o > 0; o >>= 1)
        sump += __shfl_down_sync(0xffffffffu, sump, o);
    __shared__ double psh[8];
    if (lane == 0) psh[wid] = sump;
    __syncthreads();
    if (tid == 0) {
        double s = 0.0;
        for (int w = 0; w < 8; w++) s += psh[w];
        g_sumP[batch]  = s;
        g_len[batch]   = total;
        out_len[batch] = (float)total;
    }
}

// ---------------------------------------------------------------------------
// Gather x_down
// ---------------------------------------------------------------------------
__global__ void gather_kernel(const float* __restrict__ x, float* __restrict__ x_down)
{
    const int row   = blockIdx.x;
    const int batch = row >> 13;
    const int jj    = row & (Ln - 1);
    const int tid   = threadIdx.x;

    float4* dst = (float4*)(x_down + (size_t)row * Dn);
    if (jj < g_len[batch]) {
        const int src = g_src[row];
        const float4* s = (const float4*)(x + (size_t)(batch * Ln + src) * Dn);
        dst[tid] = s[tid];
    } else {
        dst[tid] = make_float4(0.f, 0.f, 0.f, 0.f);
    }
}

__global__ void finalize_kernel(float* __restrict__ o_loss)
{
    double sb = 0.0, sp = 0.0;
    for (int i = 0; i < Bn; i++) { sb += (double)g_len[i]; sp += g_sumP[i]; }
    const double F = sb / (double)BLn;
    const double G = sp / (double)BLn;
    const double N = 6.0;
    o_loss[0] = (float)(N / (N - 1.0) * ((N - 1.0) * F * G + (1.0 - F) * (1.0 - G)));
}

// ---------------------------------------------------------------------------
// Launch. Output layout (f32): x_down | P_down | b | p | lengths | ratio_loss
// ---------------------------------------------------------------------------
extern "C" void kernel_launch(void* const* d_in, const int* in_sizes, int n_in,
                              void* d_out, int out_size)
{
    const float* x  = (const float*)d_in[0];
    const float* Wq = (const float*)d_in[1];
    const float* Wk = (const float*)d_in[2];

    float* out    = (float*)d_out;
    float* o_xd   = out;
    float* o_P    = out + (size_t)BLn * Dn;
    float* o_b    = o_P + BLn;
    float* o_p    = o_b + BLn;
    float* o_len  = o_p + BLn;
    float* o_loss = o_len + Bn;

    cudaFuncSetAttribute(hgemm_kernel,
                         cudaFuncAttributeMaxDynamicSharedMemorySize, GEMM_SMEM);
    cudaFuncSetAttribute(scan_kernel,
                         cudaFuncAttributeMaxDynamicSharedMemorySize, 2 * Ln * 4);

    const int conv_blocks = (2 * WN4 + XN4 + 255) / 256;
    conv_all_kernel<<<conv_blocks, 256>>>(x, Wq, Wk);

    hgemm_kernel<<<dim3(8, 256, 2), 256, GEMM_SMEM>>>();

    props_kernel<<<BLn / 8, 256>>>(o_p, o_b);
    fixup_partial_kernel<<<dim3(32, MAXFIX), 256>>>(x, Wq, Wk);
    fixup_apply_kernel<<<1, MAXFIX>>>(o_b);
    scan_kernel<<<Bn, 256, 2 * Ln * 4>>>(o_p, o_b, o_P, o_len);
    gather_kernel<<<BLn, 256>>>(x, o_xd);
    finalize_kernel<<<1, 1>>>(o_loss);
}